// round 15
// baseline (speedup 1.0000x reference)
#include <cuda_runtime.h>
#include <cuda_fp16.h>

// Problem constants (fixed by the dataset)
#define MAX_N 100000
#define D 128            // D_IN == D_OUT == 128
#define ROWS_PER_BLK 64
#define CAP 64           // padded-CSR bucket capacity per node
#define OVF_MAX 65536    // overflow list capacity (expected use: 0)
#define GEMM_GRID 296    // 2 blocks/SM x 148 SMs (persistent, co-resident)

// Scratch (device globals — no dynamic allocation allowed)
__device__ __align__(16) __half g_y[(size_t)MAX_N * D];  // dinv[r]*(X@W)[r], fp16
__device__ __align__(16) __half g_wt[D * D];             // W^T [n][k] (fallback)
__device__ __align__(16) uint4  g_wfrag[2048];           // W in mma B-fragment order
__device__ int    g_cnt[MAX_N];                    // in-degree / fill cursor
__device__ int    g_bucket[(size_t)MAX_N * CAP];   // source ids, grouped by dest
__device__ int    g_ovf_cnt;
__device__ int2   g_ovf[OVF_MAX];                  // (r, c) spill edges

// Grid barrier state: MONOTONIC (never reset) -> safe across graph replays.
__device__ int g_bar_ticket;   // zero-initialized at module load
__device__ int g_bar_done;

__device__ __forceinline__ void grid_barrier() {
    __syncthreads();
    if (threadIdx.x == 0) {
        __threadfence();                       // publish this block's writes
        int t = atomicAdd(&g_bar_ticket, 1);
        int inst = t / GEMM_GRID;              // barrier instance id (monotonic)
        if ((t % GEMM_GRID) == GEMM_GRID - 1) {
            atomicExch(&g_bar_done, inst + 1); // release
        } else {
            while (atomicAdd(&g_bar_done, 0) < inst + 1) __nanosleep(64);
        }
        __threadfence();                       // acquire others' writes
    }
    __syncthreads();
}

__device__ __forceinline__ void fill_edge(int r, int c, int N) {
    if (r == c) return;                                   // self-loop weight 0
    if ((unsigned)r >= (unsigned)N || (unsigned)c >= (unsigned)N) return;
    int slot = atomicAdd(&g_cnt[c], 1);
    if (slot < CAP) {
        g_bucket[(size_t)c * CAP + slot] = r;
    } else {
        int o = atomicAdd(&g_ovf_cnt, 1);
        if (o < OVF_MAX) g_ovf[o] = make_int2(r, c);
    }
}

__device__ __forceinline__ void mma16816(float* d, unsigned a0, unsigned a1,
                                         unsigned a2, unsigned a3,
                                         unsigned b0, unsigned b1) {
    asm volatile(
        "mma.sync.aligned.m16n8k16.row.col.f32.f16.f16.f32 "
        "{%0,%1,%2,%3}, {%4,%5,%6,%7}, {%8,%9}, {%0,%1,%2,%3};"
        : "+f"(d[0]), "+f"(d[1]), "+f"(d[2]), "+f"(d[3])
        : "r"(a0), "r"(a1), "r"(a2), "r"(a3), "r"(b0), "r"(b1));
}

// ---------------------------------------------------------------------------
// FUSED persistent kernel: zero+Wfrag -> barrier -> fill (+first X prefetch)
// -> barrier -> pipelined tensor GEMM (y = fp16(dinv * X@W)).
__global__ void __launch_bounds__(128, 2) k_main(const float* __restrict__ x,
                                                 const float* __restrict__ wm,
                                                 const int* __restrict__ erow,
                                                 const int* __restrict__ ecol,
                                                 int N, int E, int ntiles) {
    extern __shared__ __align__(16) unsigned char dsm[];
    int tid = threadIdx.x;
    int gtid = blockIdx.x * 128 + tid;
    const int GSTRIDE = GEMM_GRID * 128;

    // ---- phase 0: zero cursors + build Wfrag ----
    for (int i = gtid; i < N; i += GSTRIDE) g_cnt[i] = 0;
    if (gtid == 0) g_ovf_cnt = 0;
    if (gtid < 2048) {
        int lane = gtid & 31;
        int ks2  = (gtid >> 5) & 3;
        int nt   = gtid >> 7;
        int n  = nt * 8 + (lane >> 2);
        int kb = ks2 * 32 + (lane & 3) * 2;
        __half2 p0 = __floats2half2_rn(wm[(kb +  0) * D + n], wm[(kb +  1) * D + n]);
        __half2 p1 = __floats2half2_rn(wm[(kb +  8) * D + n], wm[(kb +  9) * D + n]);
        __half2 p2 = __floats2half2_rn(wm[(kb + 16) * D + n], wm[(kb + 17) * D + n]);
        __half2 p3 = __floats2half2_rn(wm[(kb + 24) * D + n], wm[(kb + 25) * D + n]);
        uint4 v;
        v.x = *(unsigned*)&p0; v.y = *(unsigned*)&p1;
        v.z = *(unsigned*)&p2; v.w = *(unsigned*)&p3;
        g_wfrag[gtid] = v;
    }
    grid_barrier();

    // ---- phase 1: stage Wfrag->smem, first X prefetch, then CSR fill ----
    int lane = tid & 31;
    int w = tid >> 5;

    uint4* wf_s = (uint4*)dsm;
#pragma unroll
    for (int i = 0; i < 16; i++) wf_s[tid + 128 * i] = g_wfrag[tid + 128 * i];

    unsigned xb[2];
    xb[0] = (unsigned)__cvta_generic_to_shared(dsm + 32768);
    xb[1] = (unsigned)__cvta_generic_to_shared(dsm + 65536);

    auto stage = [&](int b, int tile) {
#pragma unroll
        for (int i = 0; i < 16; i++) {
            int idx = tid + 128 * i;
            int r = idx >> 5, q = idx & 31;
            int gr = tile * ROWS_PER_BLK + r;
            if (gr > N - 1) gr = N - 1;          // clamp: epilogue drops r>=N
            const float* src = x + (size_t)gr * D + q * 4;
            unsigned dst = xb[b] + r * 512 + ((q ^ (r & 7)) << 4);
            asm volatile("cp.async.cg.shared.global [%0], [%1], 16;"
                         :: "r"(dst), "l"(src));
        }
    };

    int t0 = blockIdx.x;
    if (t0 < ntiles) stage(0, t0);               // overlaps with fill below
    asm volatile("cp.async.commit_group;");

    int nchunks = (E + 3) / 4;
    for (int ch = gtid; ch < nchunks; ch += GSTRIDE) {
        int e0 = ch * 4;
        if (e0 + 4 <= E) {
            int4 r4 = *(const int4*)(erow + e0);
            int4 c4 = *(const int4*)(ecol + e0);
            fill_edge(r4.x, c4.x, N);
            fill_edge(r4.y, c4.y, N);
            fill_edge(r4.z, c4.z, N);
            fill_edge(r4.w, c4.w, N);
        } else {
            for (int e = e0; e < E; e++) fill_edge(erow[e], ecol[e], N);
        }
    }
    grid_barrier();                               // cnt/bucket ready for epilogue

    // ---- phase 2: pipelined GEMM (proven R11 form) ----
    int g  = lane >> 2;
    int t4 = lane & 3;
    unsigned swz = (unsigned)g << 4;

    int buf = 0;
    for (int t = t0; t < ntiles; t += GEMM_GRID) {
        int tn = t + GEMM_GRID;
        if (tn < ntiles) stage(buf ^ 1, tn);
        asm volatile("cp.async.commit_group;");
        asm volatile("cp.async.wait_group 1;");
        __syncthreads();

        const unsigned char* xr0 =
            dsm + 32768 + buf * 32768 + (w * 16 + g) * 512;
        const unsigned char* xr8 = xr0 + 8 * 512;

        unsigned A0[8], A1[8], A2[8], A3[8];
#pragma unroll
        for (int ks = 0; ks < 8; ks++) {
            int o0 = ks * 64 + t4 * 8;
            int o2 = o0 + 32;
            int p0 = (int)(((unsigned)(o0 & ~15) ^ swz) | (unsigned)(o0 & 15));
            int p2 = (int)(((unsigned)(o2 & ~15) ^ swz) | (unsigned)(o2 & 15));
            float2 f0 = *(const float2*)(xr0 + p0);
            float2 f1 = *(const float2*)(xr8 + p0);
            float2 f2 = *(const float2*)(xr0 + p2);
            float2 f3 = *(const float2*)(xr8 + p2);
            __half2 h0 = __floats2half2_rn(f0.x, f0.y);
            __half2 h1 = __floats2half2_rn(f1.x, f1.y);
            __half2 h2 = __floats2half2_rn(f2.x, f2.y);
            __half2 h3 = __floats2half2_rn(f3.x, f3.y);
            A0[ks] = *(unsigned*)&h0;
            A1[ks] = *(unsigned*)&h1;
            A2[ks] = *(unsigned*)&h2;
            A3[ks] = *(unsigned*)&h3;
        }

        float acc[16][4];
#pragma unroll
        for (int nt = 0; nt < 16; nt++)
#pragma unroll
            for (int j = 0; j < 4; j++) acc[nt][j] = 0.f;

#pragma unroll
        for (int nt = 0; nt < 16; nt++) {
            const uint4* bf = wf_s + nt * 128 + lane;
#pragma unroll
            for (int ks2 = 0; ks2 < 4; ks2++) {
                uint4 b = bf[ks2 * 32];
                int ks = ks2 * 2;
                mma16816(acc[nt], A0[ks],   A1[ks],   A2[ks],   A3[ks],   b.x, b.y);
                mma16816(acc[nt], A0[ks+1], A1[ks+1], A2[ks+1], A3[ks+1], b.z, b.w);
            }
        }

        int block_row = t * ROWS_PER_BLK;
        int r0 = block_row + w * 16 + g;
        int r1 = r0 + 8;
        float s0 = (r0 < N) ? rsqrtf((float)(g_cnt[r0] + 1)) : 0.f;
        float s1 = (r1 < N) ? rsqrtf((float)(g_cnt[r1] + 1)) : 0.f;
#pragma unroll
        for (int nt = 0; nt < 16; nt++) {
            int col = nt * 8 + t4 * 2;
            if (r0 < N) {
                __half2 h = __floats2half2_rn(acc[nt][0] * s0, acc[nt][1] * s0);
                *(__half2*)(g_y + (size_t)r0 * D + col) = h;
            }
            if (r1 < N) {
                __half2 h = __floats2half2_rn(acc[nt][2] * s1, acc[nt][3] * s1);
                *(__half2*)(g_y + (size_t)r1 * D + col) = h;
            }
        }
        __syncthreads();
        buf ^= 1;
    }
}

// ---------------------------------------------------------------------------
// FALLBACK path (attribute rejected): separate prep / fill / 48KB gemm.
__global__ void k_prep(const float* __restrict__ w, int N) {
    int idx = blockIdx.x * blockDim.x + threadIdx.x;
    if (idx < N) g_cnt[idx] = 0;
    if (idx == 0) g_ovf_cnt = 0;
    if (idx < D * D / 2) {
        int kk = idx & 63;
        int n  = idx >> 6;
        __half2 h = __floats2half2_rn(w[(2 * kk + 0) * D + n],
                                      w[(2 * kk + 1) * D + n]);
        *(__half2*)(g_wt + n * D + 2 * kk) = h;
    }
}

__global__ void k_fill(const int* __restrict__ row,
                       const int* __restrict__ col, int E, int N) {
    int t = blockIdx.x * blockDim.x + threadIdx.x;
    int e0 = t * 4;
    if (e0 + 4 <= E) {
        int4 r4 = *(const int4*)(row + e0);
        int4 c4 = *(const int4*)(col + e0);
        fill_edge(r4.x, c4.x, N);
        fill_edge(r4.y, c4.y, N);
        fill_edge(r4.z, c4.z, N);
        fill_edge(r4.w, c4.w, N);
    } else {
        for (int e = e0; e < E; e++) fill_edge(row[e], col[e], N);
    }
}

__global__ void k_gemm48(const float* __restrict__ x, int N) {
    __shared__ __align__(16) unsigned char sm[49152];
    int tid = threadIdx.x;
    int lane = tid & 31;
    int w = tid >> 5;
    int block_row = blockIdx.x * ROWS_PER_BLK;

    const uint4* wt4 = (const uint4*)g_wt;
#pragma unroll
    for (int i = 0; i < 16; i++) {
        int idx = tid + 128 * i;
        int n = idx >> 4, c = idx & 15;
        uint4 v = wt4[idx];
        *(uint4*)(sm + 16384 + n * 256 + ((c ^ (n & 7)) << 4)) = v;
    }
    const float4* x4 = (const float4*)x;
#pragma unroll
    for (int i = 0; i < 16; i++) {
        int idx = tid + 128 * i;
        int r = idx >> 5, q = idx & 31;
        int gr = block_row + r;
        float4 v = make_float4(0.f, 0.f, 0.f, 0.f);
        if (gr < N) v = x4[(size_t)gr * 32 + q];
        __half2 h0 = __floats2half2_rn(v.x, v.y);
        __half2 h1 = __floats2half2_rn(v.z, v.w);
        uint2 p;
        p.x = *(unsigned*)&h0;
        p.y = *(unsigned*)&h1;
        int byte = r * 256 + q * 8;
        *(uint2*)(sm + (byte ^ ((r & 7) << 4))) = p;
    }
    __syncthreads();

    int g = lane >> 2, t4 = lane & 3;
    int swz = g << 4;
    float acc[16][4];
#pragma unroll
    for (int nt = 0; nt < 16; nt++)
#pragma unroll
        for (int j = 0; j < 4; j++) acc[nt][j] = 0.f;

    const unsigned char* xrow0 = sm + (w * 16 + g) * 256;
    const unsigned char* xrow8 = xrow0 + 8 * 256;
    const unsigned char* wbase = sm + 16384 + g * 256;
#pragma unroll
    for (int ks = 0; ks < 8; ks++) {
        int kb = ks * 32 + t4 * 4;
        unsigned a0 = *(const unsigned*)(xrow0 + ( kb       ^ swz));
        unsigned a1 = *(const unsigned*)(xrow8 + ( kb       ^ swz));
        unsigned a2 = *(const unsigned*)(xrow0 + ((kb + 16) ^ swz));
        unsigned a3 = *(const unsigned*)(xrow8 + ((kb + 16) ^ swz));
#pragma unroll
        for (int nt = 0; nt < 16; nt++) {
            const unsigned char* wp = wbase + nt * 8 * 256;
            unsigned b0 = *(const unsigned*)(wp + ( kb       ^ swz));
            unsigned b1 = *(const unsigned*)(wp + ((kb + 16) ^ swz));
            mma16816(acc[nt], a0, a1, a2, a3, b0, b1);
        }
    }
    int r0 = block_row + w * 16 + g;
    int r1 = r0 + 8;
    float s0 = (r0 < N) ? rsqrtf((float)(g_cnt[r0] + 1)) : 0.f;
    float s1 = (r1 < N) ? rsqrtf((float)(g_cnt[r1] + 1)) : 0.f;
#pragma unroll
    for (int nt = 0; nt < 16; nt++) {
        int col = nt * 8 + t4 * 2;
        if (r0 < N) {
            __half2 h = __floats2half2_rn(acc[nt][0] * s0, acc[nt][1] * s0);
            *(__half2*)(g_y + (size_t)r0 * D + col) = h;
        }
        if (r1 < N) {
            __half2 h = __floats2half2_rn(acc[nt][2] * s1, acc[nt][3] * s1);
            *(__half2*)(g_y + (size_t)r1 * D + col) = h;
        }
    }
}

// ---------------------------------------------------------------------------
// helper: acc[0..7] += sel * fp16x8(raw)
__device__ __forceinline__ void acc_row16(float* acc, float4 raw, float sel) {
    unsigned u0 = __float_as_uint(raw.x);
    unsigned u1 = __float_as_uint(raw.y);
    unsigned u2 = __float_as_uint(raw.z);
    unsigned u3 = __float_as_uint(raw.w);
    float2 f0 = __half22float2(*(__half2*)&u0);
    float2 f1 = __half22float2(*(__half2*)&u1);
    float2 f2 = __half22float2(*(__half2*)&u2);
    float2 f3 = __half22float2(*(__half2*)&u3);
    acc[0] = fmaf(sel, f0.x, acc[0]); acc[1] = fmaf(sel, f0.y, acc[1]);
    acc[2] = fmaf(sel, f1.x, acc[2]); acc[3] = fmaf(sel, f1.y, acc[3]);
    acc[4] = fmaf(sel, f2.x, acc[4]); acc[5] = fmaf(sel, f2.y, acc[5]);
    acc[6] = fmaf(sel, f3.x, acc[6]); acc[7] = fmaf(sel, f3.y, acc[7]);
}

// per-destination accumulate: TWO nodes per warp, 16 lanes per node row.
// out[c] = bias + dinv_c * (sum_r y[r] + y[c]); inline spill scan. [R14, roofline]
__global__ void k_acc(const float* __restrict__ bias,
                      float* __restrict__ out, int N) {
    int lane = threadIdx.x & 31;
    int hl   = lane & 15;
    int wid  = (blockIdx.x * blockDim.x + threadIdx.x) >> 5;
    int c0 = 2 * wid;
    if (c0 >= N) return;
    int c = c0 + (lane >> 4);
    if (c >= N) c = c0;

    int cnt_full = g_cnt[c];
    int cnt = cnt_full > CAP ? CAP : cnt_full;
    int maxcnt = max(cnt, __shfl_xor_sync(0xffffffffu, cnt, 16));

    float acc[8];
#pragma unroll
    for (int i = 0; i < 8; i++) acc[i] = 0.f;

    acc_row16(acc, __ldg((const float4*)(g_y + (size_t)c * D) + hl), 1.f);

    const int* base = g_bucket + (size_t)c * CAP;
    for (int k = 0; k * 16 < maxcnt; k++) {
        int ids = __ldg(base + k * 16 + hl);
#pragma unroll
        for (int j = 0; j < 16; j += 4) {
            if (k * 16 + j >= maxcnt) break;   // warp-uniform
            int r0 = __shfl_sync(0xffffffffu, ids, j + 0, 16);
            int r1 = __shfl_sync(0xffffffffu, ids, j + 1, 16);
            int r2 = __shfl_sync(0xffffffffu, ids, j + 2, 16);
            int r3 = __shfl_sync(0xffffffffu, ids, j + 3, 16);
            float4 g0 = __ldg((const float4*)(g_y + (size_t)r0 * D) + hl);
            float4 g1 = __ldg((const float4*)(g_y + (size_t)r1 * D) + hl);
            float4 g2 = __ldg((const float4*)(g_y + (size_t)r2 * D) + hl);
            float4 g3 = __ldg((const float4*)(g_y + (size_t)r3 * D) + hl);
            int b = k * 16 + j;
            acc_row16(acc, g0, b + 0 < cnt ? 1.f : 0.f);
            acc_row16(acc, g1, b + 1 < cnt ? 1.f : 0.f);
            acc_row16(acc, g2, b + 2 < cnt ? 1.f : 0.f);
            acc_row16(acc, g3, b + 3 < cnt ? 1.f : 0.f);
        }
    }

    if (cnt_full > CAP || __shfl_xor_sync(0xffffffffu, cnt_full, 16) > CAP) {
        int ovf = g_ovf_cnt;
        if (ovf > OVF_MAX) ovf = OVF_MAX;
        for (int o = 0; o < ovf; o++) {
            int2 e = g_ovf[o];
            if (e.y == c) {
                float4 gr = __ldg((const float4*)(g_y + (size_t)e.x * D) + hl);
                acc_row16(acc, gr, 1.f);
            }
        }
    }

    float s = rsqrtf((float)(cnt_full + 1));
    float4 bv0 = __ldg((const float4*)bias + 2 * hl);
    float4 bv1 = __ldg((const float4*)bias + 2 * hl + 1);
    float4* o4 = (float4*)(out + (size_t)c * D);
    o4[2 * hl] = make_float4(fmaf(s, acc[0], bv0.x), fmaf(s, acc[1], bv0.y),
                             fmaf(s, acc[2], bv0.z), fmaf(s, acc[3], bv0.w));
    o4[2 * hl + 1] = make_float4(fmaf(s, acc[4], bv1.x), fmaf(s, acc[5], bv1.y),
                                 fmaf(s, acc[6], bv1.z), fmaf(s, acc[7], bv1.w));
}

extern "C" void kernel_launch(void* const* d_in, const int* in_sizes, int n_in,
                              void* d_out, int out_size) {
    const float* x    = (const float*)d_in[0];
    const int*   ei   = (const int*)d_in[1];     // int32 edge_index [2, E]
    const float* w    = (const float*)d_in[2];
    const float* bias = (const float*)d_in[3];
    float*       out  = (float*)d_out;

    int N = in_sizes[0] / D;
    int E = in_sizes[1] / 2;
    const int* row = ei;
    const int* col = ei + E;
    int ntiles = (N + ROWS_PER_BLK - 1) / ROWS_PER_BLK;

    cudaError_t rc = cudaFuncSetAttribute(
        k_main, cudaFuncAttributeMaxDynamicSharedMemorySize, 98304);
    if (rc == cudaSuccess) {
        k_main<<<GEMM_GRID, 128, 98304>>>(x, w, row, col, N, E, ntiles);
    } else {
        (void)cudaGetLastError();   // clear sticky error from rejected attribute
        k_prep<<<(N + 255) / 256, 256>>>(w, N);
        int fthreads = (E + 3) / 4;
        k_fill<<<(fthreads + 255) / 256, 256>>>(row, col, E, N);
        k_gemm48<<<ntiles, 128>>>(x, N);
    }

    int warps = (N + 1) / 2;
    k_acc<<<(warps * 32 + 255) / 256, 256>>>(bias, out, N);
}

// round 16
// speedup vs baseline: 1.1450x; 1.1450x over previous
#include <cuda_runtime.h>
#include <cuda_fp16.h>

// Problem constants (fixed by the dataset)
#define MAX_N 100000
#define D 128            // D_IN == D_OUT == 128
#define ROWS_PER_BLK 64
#define CAP 64           // padded-CSR bucket capacity per node
#define OVF_MAX 65536    // overflow list capacity (expected use: 0)
#define GEMM_GRID 296    // 2 blocks/SM x 148 SMs (persistent)

// Scratch (device globals — zero-initialized at module load).
// INVARIANT: g_cnt[] and g_ovf_cnt are 0 on entry to every kernel_launch call
// (initially from load-time zero-init; thereafter re-zeroed at the end of
// k_acc). Every call performs identical work -> deterministic, replay-safe.
__device__ __align__(16) __half g_y[(size_t)MAX_N * D];  // dinv[r]*(X@W)[r], fp16
__device__ __align__(16) __half g_wt[D * D];             // W^T [n][k] (fallback)
__device__ __align__(16) uint4  g_wfrag[2048];           // W in mma B-fragment order
__device__ int    g_cnt[MAX_N];                    // in-degree / fill cursor
__device__ int    g_bucket[(size_t)MAX_N * CAP];   // source ids, grouped by dest
__device__ int    g_ovf_cnt;
__device__ int2   g_ovf[OVF_MAX];                  // (r, c) spill edges

// ---------------------------------------------------------------------------
__device__ __forceinline__ void fill_edge(int r, int c, int N) {
    if (r == c) return;                                   // self-loop weight 0
    if ((unsigned)r >= (unsigned)N || (unsigned)c >= (unsigned)N) return;
    int slot = atomicAdd(&g_cnt[c], 1);
    if (slot < CAP) {
        g_bucket[(size_t)c * CAP + slot] = r;
    } else {
        int o = atomicAdd(&g_ovf_cnt, 1);
        if (o < OVF_MAX) g_ovf[o] = make_int2(r, c);
    }
}

// 1) build padded CSR (4 edges/thread, int4 reads) + build Wfrag (first 2048
//    global threads). Cursors arrive already zeroed (see invariant above).
__global__ void k_fill(const int* __restrict__ row,
                       const int* __restrict__ col,
                       const float* __restrict__ wm, int E, int N) {
    int t = blockIdx.x * blockDim.x + threadIdx.x;

    if (t < 2048) {   // W -> mma B-fragment order (independent of cursors)
        int lane = t & 31;
        int ks2  = (t >> 5) & 3;
        int nt   = t >> 7;
        int n  = nt * 8 + (lane >> 2);
        int kb = ks2 * 32 + (lane & 3) * 2;
        __half2 p0 = __floats2half2_rn(wm[(kb +  0) * D + n], wm[(kb +  1) * D + n]);
        __half2 p1 = __floats2half2_rn(wm[(kb +  8) * D + n], wm[(kb +  9) * D + n]);
        __half2 p2 = __floats2half2_rn(wm[(kb + 16) * D + n], wm[(kb + 17) * D + n]);
        __half2 p3 = __floats2half2_rn(wm[(kb + 24) * D + n], wm[(kb + 25) * D + n]);
        uint4 v;
        v.x = *(unsigned*)&p0; v.y = *(unsigned*)&p1;
        v.z = *(unsigned*)&p2; v.w = *(unsigned*)&p3;
        g_wfrag[t] = v;
    }

    int e0 = t * 4;
    if (e0 + 4 <= E) {
        int4 r4 = *(const int4*)(row + e0);
        int4 c4 = *(const int4*)(col + e0);
        fill_edge(r4.x, c4.x, N);
        fill_edge(r4.y, c4.y, N);
        fill_edge(r4.z, c4.z, N);
        fill_edge(r4.w, c4.w, N);
    } else {
        for (int e = e0; e < E; e++) fill_edge(row[e], col[e], N);
    }
}

// ---------------------------------------------------------------------------
__device__ __forceinline__ void mma16816(float* d, unsigned a0, unsigned a1,
                                         unsigned a2, unsigned a3,
                                         unsigned b0, unsigned b1) {
    asm volatile(
        "mma.sync.aligned.m16n8k16.row.col.f32.f16.f16.f32 "
        "{%0,%1,%2,%3}, {%4,%5,%6,%7}, {%8,%9}, {%0,%1,%2,%3};"
        : "+f"(d[0]), "+f"(d[1]), "+f"(d[2]), "+f"(d[3])
        : "r"(a0), "r"(a1), "r"(a2), "r"(a3), "r"(b0), "r"(b1));
}

// 2a) PRIMARY GEMM: persistent, cp.async double-buffered, pre-fragmented B.
//     [R11/R14 proven form; y = fp16(dinv*XW) in epilogue]
__global__ void __launch_bounds__(128, 2) k_gemm_pipe(const float* __restrict__ x,
                                                      int N, int ntiles) {
    extern __shared__ __align__(16) unsigned char dsm[];

    int tid = threadIdx.x;
    int lane = tid & 31;
    int w = tid >> 5;

    uint4* wf_s = (uint4*)dsm;
#pragma unroll
    for (int i = 0; i < 16; i++) wf_s[tid + 128 * i] = g_wfrag[tid + 128 * i];

    unsigned xb[2];
    xb[0] = (unsigned)__cvta_generic_to_shared(dsm + 32768);
    xb[1] = (unsigned)__cvta_generic_to_shared(dsm + 65536);

    auto stage = [&](int b, int tile) {
#pragma unroll
        for (int i = 0; i < 16; i++) {
            int idx = tid + 128 * i;
            int r = idx >> 5, q = idx & 31;
            int gr = tile * ROWS_PER_BLK + r;
            if (gr > N - 1) gr = N - 1;          // clamp: epilogue drops r>=N
            const float* src = x + (size_t)gr * D + q * 4;
            unsigned dst = xb[b] + r * 512 + ((q ^ (r & 7)) << 4);
            asm volatile("cp.async.cg.shared.global [%0], [%1], 16;"
                         :: "r"(dst), "l"(src));
        }
    };

    int g  = lane >> 2;
    int t4 = lane & 3;
    unsigned swz = (unsigned)g << 4;

    int t = blockIdx.x;
    if (t < ntiles) stage(0, t);
    asm volatile("cp.async.commit_group;");

    int buf = 0;
    for (; t < ntiles; t += GEMM_GRID) {
        int tn = t + GEMM_GRID;
        if (tn < ntiles) stage(buf ^ 1, tn);
        asm volatile("cp.async.commit_group;");
        asm volatile("cp.async.wait_group 1;");
        __syncthreads();

        const unsigned char* xr0 =
            dsm + 32768 + buf * 32768 + (w * 16 + g) * 512;
        const unsigned char* xr8 = xr0 + 8 * 512;

        unsigned A0[8], A1[8], A2[8], A3[8];
#pragma unroll
        for (int ks = 0; ks < 8; ks++) {
            int o0 = ks * 64 + t4 * 8;
            int o2 = o0 + 32;
            int p0 = (int)(((unsigned)(o0 & ~15) ^ swz) | (unsigned)(o0 & 15));
            int p2 = (int)(((unsigned)(o2 & ~15) ^ swz) | (unsigned)(o2 & 15));
            float2 f0 = *(const float2*)(xr0 + p0);
            float2 f1 = *(const float2*)(xr8 + p0);
            float2 f2 = *(const float2*)(xr0 + p2);
            float2 f3 = *(const float2*)(xr8 + p2);
            __half2 h0 = __floats2half2_rn(f0.x, f0.y);
            __half2 h1 = __floats2half2_rn(f1.x, f1.y);
            __half2 h2 = __floats2half2_rn(f2.x, f2.y);
            __half2 h3 = __floats2half2_rn(f3.x, f3.y);
            A0[ks] = *(unsigned*)&h0;
            A1[ks] = *(unsigned*)&h1;
            A2[ks] = *(unsigned*)&h2;
            A3[ks] = *(unsigned*)&h3;
        }

        float acc[16][4];
#pragma unroll
        for (int nt = 0; nt < 16; nt++)
#pragma unroll
            for (int j = 0; j < 4; j++) acc[nt][j] = 0.f;

#pragma unroll
        for (int nt = 0; nt < 16; nt++) {
            const uint4* bf = wf_s + nt * 128 + lane;
#pragma unroll
            for (int ks2 = 0; ks2 < 4; ks2++) {
                uint4 b = bf[ks2 * 32];
                int ks = ks2 * 2;
                mma16816(acc[nt], A0[ks],   A1[ks],   A2[ks],   A3[ks],   b.x, b.y);
                mma16816(acc[nt], A0[ks+1], A1[ks+1], A2[ks+1], A3[ks+1], b.z, b.w);
            }
        }

        int block_row = t * ROWS_PER_BLK;
        int r0 = block_row + w * 16 + g;
        int r1 = r0 + 8;
        float s0 = (r0 < N) ? rsqrtf((float)(g_cnt[r0] + 1)) : 0.f;
        float s1 = (r1 < N) ? rsqrtf((float)(g_cnt[r1] + 1)) : 0.f;
#pragma unroll
        for (int nt = 0; nt < 16; nt++) {
            int col = nt * 8 + t4 * 2;
            if (r0 < N) {
                __half2 h = __floats2half2_rn(acc[nt][0] * s0, acc[nt][1] * s0);
                *(__half2*)(g_y + (size_t)r0 * D + col) = h;
            }
            if (r1 < N) {
                __half2 h = __floats2half2_rn(acc[nt][2] * s1, acc[nt][3] * s1);
                *(__half2*)(g_y + (size_t)r1 * D + col) = h;
            }
        }
        __syncthreads();
        buf ^= 1;
    }
}

// 2b) FALLBACK path helpers (attribute rejected): build g_wt, then 48KB gemm.
__global__ void k_prep_fb(const float* __restrict__ w) {
    int idx = blockIdx.x * blockDim.x + threadIdx.x;
    if (idx < D * D / 2) {
        int kk = idx & 63;
        int n  = idx >> 6;
        __half2 h = __floats2half2_rn(w[(2 * kk + 0) * D + n],
                                      w[(2 * kk + 1) * D + n]);
        *(__half2*)(g_wt + n * D + 2 * kk) = h;
    }
}

__global__ void k_gemm48(const float* __restrict__ x, int N) {
    __shared__ __align__(16) unsigned char sm[49152];
    int tid = threadIdx.x;
    int lane = tid & 31;
    int w = tid >> 5;
    int block_row = blockIdx.x * ROWS_PER_BLK;

    const uint4* wt4 = (const uint4*)g_wt;
#pragma unroll
    for (int i = 0; i < 16; i++) {
        int idx = tid + 128 * i;
        int n = idx >> 4, c = idx & 15;
        uint4 v = wt4[idx];
        *(uint4*)(sm + 16384 + n * 256 + ((c ^ (n & 7)) << 4)) = v;
    }
    const float4* x4 = (const float4*)x;
#pragma unroll
    for (int i = 0; i < 16; i++) {
        int idx = tid + 128 * i;
        int r = idx >> 5, q = idx & 31;
        int gr = block_row + r;
        float4 v = make_float4(0.f, 0.f, 0.f, 0.f);
        if (gr < N) v = x4[(size_t)gr * 32 + q];
        __half2 h0 = __floats2half2_rn(v.x, v.y);
        __half2 h1 = __floats2half2_rn(v.z, v.w);
        uint2 p;
        p.x = *(unsigned*)&h0;
        p.y = *(unsigned*)&h1;
        int byte = r * 256 + q * 8;
        *(uint2*)(sm + (byte ^ ((r & 7) << 4))) = p;
    }
    __syncthreads();

    int g = lane >> 2, t4 = lane & 3;
    int swz = g << 4;
    float acc[16][4];
#pragma unroll
    for (int nt = 0; nt < 16; nt++)
#pragma unroll
        for (int j = 0; j < 4; j++) acc[nt][j] = 0.f;

    const unsigned char* xrow0 = sm + (w * 16 + g) * 256;
    const unsigned char* xrow8 = xrow0 + 8 * 256;
    const unsigned char* wbase = sm + 16384 + g * 256;
#pragma unroll
    for (int ks = 0; ks < 8; ks++) {
        int kb = ks * 32 + t4 * 4;
        unsigned a0 = *(const unsigned*)(xrow0 + ( kb       ^ swz));
        unsigned a1 = *(const unsigned*)(xrow8 + ( kb       ^ swz));
        unsigned a2 = *(const unsigned*)(xrow0 + ((kb + 16) ^ swz));
        unsigned a3 = *(const unsigned*)(xrow8 + ((kb + 16) ^ swz));
#pragma unroll
        for (int nt = 0; nt < 16; nt++) {
            const unsigned char* wp = wbase + nt * 8 * 256;
            unsigned b0 = *(const unsigned*)(wp + ( kb       ^ swz));
            unsigned b1 = *(const unsigned*)(wp + ((kb + 16) ^ swz));
            mma16816(acc[nt], a0, a1, a2, a3, b0, b1);
        }
    }
    int r0 = block_row + w * 16 + g;
    int r1 = r0 + 8;
    float s0 = (r0 < N) ? rsqrtf((float)(g_cnt[r0] + 1)) : 0.f;
    float s1 = (r1 < N) ? rsqrtf((float)(g_cnt[r1] + 1)) : 0.f;
#pragma unroll
    for (int nt = 0; nt < 16; nt++) {
        int col = nt * 8 + t4 * 2;
        if (r0 < N) {
            __half2 h = __floats2half2_rn(acc[nt][0] * s0, acc[nt][1] * s0);
            *(__half2*)(g_y + (size_t)r0 * D + col) = h;
        }
        if (r1 < N) {
            __half2 h = __floats2half2_rn(acc[nt][2] * s1, acc[nt][3] * s1);
            *(__half2*)(g_y + (size_t)r1 * D + col) = h;
        }
    }
}

// ---------------------------------------------------------------------------
// helper: acc[0..7] += sel * fp16x8(raw)
__device__ __forceinline__ void acc_row16(float* acc, float4 raw, float sel) {
    unsigned u0 = __float_as_uint(raw.x);
    unsigned u1 = __float_as_uint(raw.y);
    unsigned u2 = __float_as_uint(raw.z);
    unsigned u3 = __float_as_uint(raw.w);
    float2 f0 = __half22float2(*(__half2*)&u0);
    float2 f1 = __half22float2(*(__half2*)&u1);
    float2 f2 = __half22float2(*(__half2*)&u2);
    float2 f3 = __half22float2(*(__half2*)&u3);
    acc[0] = fmaf(sel, f0.x, acc[0]); acc[1] = fmaf(sel, f0.y, acc[1]);
    acc[2] = fmaf(sel, f1.x, acc[2]); acc[3] = fmaf(sel, f1.y, acc[3]);
    acc[4] = fmaf(sel, f2.x, acc[4]); acc[5] = fmaf(sel, f2.y, acc[5]);
    acc[6] = fmaf(sel, f3.x, acc[6]); acc[7] = fmaf(sel, f3.y, acc[7]);
}

// 3) per-destination accumulate: TWO nodes per warp, 16 lanes per node row.
//    out[c] = bias + dinv_c * (sum_r y[r] + y[c]); inline spill scan.
//    FINAL STEP: re-zero this node's cursor (restores the call invariant and
//    eliminates the separate zeroing launch). Each warp is the exclusive
//    last reader of g_cnt[c], so the reset is race-free.
__global__ void k_acc(const float* __restrict__ bias,
                      float* __restrict__ out, int N) {
    int lane = threadIdx.x & 31;
    int hl   = lane & 15;
    int wid  = (blockIdx.x * blockDim.x + threadIdx.x) >> 5;
    int c0 = 2 * wid;
    if (c0 >= N) return;
    int c = c0 + (lane >> 4);
    if (c >= N) c = c0;

    int cnt_full = g_cnt[c];
    int cnt = cnt_full > CAP ? CAP : cnt_full;
    int maxcnt = max(cnt, __shfl_xor_sync(0xffffffffu, cnt, 16));

    float acc[8];
#pragma unroll
    for (int i = 0; i < 8; i++) acc[i] = 0.f;

    acc_row16(acc, __ldg((const float4*)(g_y + (size_t)c * D) + hl), 1.f);

    const int* base = g_bucket + (size_t)c * CAP;
    for (int k = 0; k * 16 < maxcnt; k++) {
        int ids = __ldg(base + k * 16 + hl);
#pragma unroll
        for (int j = 0; j < 16; j += 4) {
            if (k * 16 + j >= maxcnt) break;   // warp-uniform
            int r0 = __shfl_sync(0xffffffffu, ids, j + 0, 16);
            int r1 = __shfl_sync(0xffffffffu, ids, j + 1, 16);
            int r2 = __shfl_sync(0xffffffffu, ids, j + 2, 16);
            int r3 = __shfl_sync(0xffffffffu, ids, j + 3, 16);
            float4 g0 = __ldg((const float4*)(g_y + (size_t)r0 * D) + hl);
            float4 g1 = __ldg((const float4*)(g_y + (size_t)r1 * D) + hl);
            float4 g2 = __ldg((const float4*)(g_y + (size_t)r2 * D) + hl);
            float4 g3 = __ldg((const float4*)(g_y + (size_t)r3 * D) + hl);
            int b = k * 16 + j;
            acc_row16(acc, g0, b + 0 < cnt ? 1.f : 0.f);
            acc_row16(acc, g1, b + 1 < cnt ? 1.f : 0.f);
            acc_row16(acc, g2, b + 2 < cnt ? 1.f : 0.f);
            acc_row16(acc, g3, b + 3 < cnt ? 1.f : 0.f);
        }
    }

    // inline spill handling (branch never taken unless a node exceeds CAP)
    if (cnt_full > CAP || __shfl_xor_sync(0xffffffffu, cnt_full, 16) > CAP) {
        int ovf = g_ovf_cnt;
        if (ovf > OVF_MAX) ovf = OVF_MAX;
        for (int o = 0; o < ovf; o++) {
            int2 e = g_ovf[o];
            if (e.y == c) {
                float4 gr = __ldg((const float4*)(g_y + (size_t)e.x * D) + hl);
                acc_row16(acc, gr, 1.f);
            }
        }
    }

    float s = rsqrtf((float)(cnt_full + 1));
    float4 bv0 = __ldg((const float4*)bias + 2 * hl);
    float4 bv1 = __ldg((const float4*)bias + 2 * hl + 1);
    float4* o4 = (float4*)(out + (size_t)c * D);
    o4[2 * hl] = make_float4(fmaf(s, acc[0], bv0.x), fmaf(s, acc[1], bv0.y),
                             fmaf(s, acc[2], bv0.z), fmaf(s, acc[3], bv0.w));
    o4[2 * hl + 1] = make_float4(fmaf(s, acc[4], bv1.x), fmaf(s, acc[5], bv1.y),
                                 fmaf(s, acc[6], bv1.z), fmaf(s, acc[7], bv1.w));

    // restore the zeroed-cursor invariant for the next call / replay
    if (hl == 0) g_cnt[c] = 0;
    if (wid == 0 && lane == 0) g_ovf_cnt = 0;
}

extern "C" void kernel_launch(void* const* d_in, const int* in_sizes, int n_in,
                              void* d_out, int out_size) {
    const float* x    = (const float*)d_in[0];
    const int*   ei   = (const int*)d_in[1];     // int32 edge_index [2, E]
    const float* w    = (const float*)d_in[2];
    const float* bias = (const float*)d_in[3];
    float*       out  = (float*)d_out;

    int N = in_sizes[0] / D;
    int E = in_sizes[1] / 2;
    const int* row = ei;
    const int* col = ei + E;
    int ntiles = (N + ROWS_PER_BLK - 1) / ROWS_PER_BLK;

    int fthreads = (E + 3) / 4;
    if (fthreads < 2048) fthreads = 2048;        // ensure Wfrag builders exist
    k_fill<<<(fthreads + 255) / 256, 256>>>(row, col, w, E, N);

    cudaError_t rc = cudaFuncSetAttribute(
        k_gemm_pipe, cudaFuncAttributeMaxDynamicSharedMemorySize, 98304);
    if (rc == cudaSuccess) {
        k_gemm_pipe<<<GEMM_GRID, 128, 98304>>>(x, N, ntiles);
    } else {
        (void)cudaGetLastError();   // clear sticky error from rejected attribute
        k_prep_fb<<<(D * D / 2 + 255) / 256, 256>>>(w);
        k_gemm48<<<ntiles, 128>>>(x, N);
    }

    int warps = (N + 1) / 2;
    k_acc<<<(warps * 32 + 255) / 256, 256>>>(bias, out, N);
}